// round 1
// baseline (speedup 1.0000x reference)
#include <cuda_runtime.h>
#include <math.h>

#define NN 4096
#define NFEAT 4096
#define NC 8
#define NH 4
#define NCOL 32
#define ALPHA 0.2f

// Scratch (no allocations allowed)
__device__ float g_Wh[NN * NCOL];     // [n][h*8+o]
__device__ float g_ss[NH * NN];       // s_src
__device__ float g_sd[NH * NN];       // s_dst
__device__ float g_smax[NH];          // global max of s_dst per head
__device__ float g_ls[NN * NC];       // log_softmax(node_embeddings)

// ---------------- K1: Wh = x @ W  (+ s_src / s_dst) ----------------
#define K1_ROWS 16
#define K1_KC 128
#define K1_THREADS 128

__global__ __launch_bounds__(K1_THREADS) void k1_gemm(
    const float* __restrict__ x, const float* __restrict__ W, const float* __restrict__ a)
{
    __shared__ float sx[K1_ROWS * 132];   // padded: bank-conflict-free row broadcast
    __shared__ float sW[K1_KC * 32];
    const int tid = threadIdx.x;
    const int i0 = blockIdx.x * K1_ROWS;
    const int r = tid >> 3, g = tid & 7;  // 8 threads per row, 4 output cols each
    float acc0 = 0.f, acc1 = 0.f, acc2 = 0.f, acc3 = 0.f;

    for (int k0 = 0; k0 < NFEAT; k0 += K1_KC) {
        // x tile: 16 rows x 128 k  (512 float4)
        #pragma unroll
        for (int it = 0; it < 4; it++) {
            int idx = tid + it * K1_THREADS;
            int rr = idx >> 5, kk4 = idx & 31;
            float4 v = *(const float4*)(x + (size_t)(i0 + rr) * NFEAT + k0 + kk4 * 4);
            float* d = sx + rr * 132 + kk4 * 4;
            d[0] = v.x; d[1] = v.y; d[2] = v.z; d[3] = v.w;
        }
        // W tile: 128 k x 32 cols (col = h*8+o), 1024 float4
        #pragma unroll
        for (int it = 0; it < 8; it++) {
            int idx = tid + it * K1_THREADS;
            int kk = idx >> 3, c4 = idx & 7;
            int h = c4 >> 1, o4 = (c4 & 1) * 4;
            float4 v = *(const float4*)(W + (size_t)h * NFEAT * NC + (size_t)(k0 + kk) * NC + o4);
            float* d = sW + kk * 32 + c4 * 4;
            d[0] = v.x; d[1] = v.y; d[2] = v.z; d[3] = v.w;
        }
        __syncthreads();
        const float* sxr = sx + r * 132;
        const float4* sW4 = (const float4*)sW;
        #pragma unroll 8
        for (int kk = 0; kk < K1_KC; kk++) {
            float xv = sxr[kk];
            float4 w4 = sW4[kk * 8 + g];
            acc0 += xv * w4.x; acc1 += xv * w4.y;
            acc2 += xv * w4.z; acc3 += xv * w4.w;
        }
        __syncthreads();
    }
    const int row = i0 + r;
    *(float4*)(g_Wh + (size_t)row * NCOL + g * 4) = make_float4(acc0, acc1, acc2, acc3);

    // s_src = Wh . a[h, :8],  s_dst = Wh . a[h, 8:]
    const int h = g >> 1;
    const int ob = (g & 1) * 4;
    const float* ah = a + h * 2 * NC;
    float ps = acc0 * ah[ob] + acc1 * ah[ob + 1] + acc2 * ah[ob + 2] + acc3 * ah[ob + 3];
    float pd = acc0 * ah[NC + ob] + acc1 * ah[NC + ob + 1] + acc2 * ah[NC + ob + 2] + acc3 * ah[NC + ob + 3];
    ps += __shfl_down_sync(0xffffffffu, ps, 1);
    pd += __shfl_down_sync(0xffffffffu, pd, 1);
    if ((g & 1) == 0) {
        g_ss[h * NN + row] = ps;
        g_sd[h * NN + row] = pd;
    }
}

// ---------------- K1b: global max of s_dst per head ----------------
__global__ void k_smax()
{
    __shared__ float sm[256];
    const int h = blockIdx.x, tid = threadIdx.x;
    float m = -1e30f;
    for (int j = tid; j < NN; j += 256) m = fmaxf(m, g_sd[h * NN + j]);
    sm[tid] = m;
    __syncthreads();
    for (int s2 = 128; s2 > 0; s2 >>= 1) {
        if (tid < s2) sm[tid] = fmaxf(sm[tid], sm[tid + s2]);
        __syncthreads();
    }
    if (tid == 0) g_smax[h] = sm[0];
}

// ---------------- K2: masked softmax attention + aggregate ----------------
#define K2_ROWS 16
#define K2_JC 128
#define K2_THREADS 128

__global__ __launch_bounds__(K2_THREADS) void k2_attn(
    const int* __restrict__ adj, float* __restrict__ dout)
{
    __shared__ float sWh[K2_JC * 36];       // padded for conflict-free float4 reads
    __shared__ float ssd[NH * K2_JC];
    const int tid = threadIdx.x;
    const int i0 = blockIdx.x * K2_ROWS;
    const int r = tid >> 3, s = tid & 7;    // 8 threads per row
    const int row = i0 + r;

    float ssr[NH], Mr[NH], l[NH];
    float acc[NH][NC];
    #pragma unroll
    for (int h = 0; h < NH; h++) {
        float ssv = g_ss[h * NN + row];
        ssr[h] = ssv;
        float t = ssv + g_smax[h];
        Mr[h] = fmaxf(t, ALPHA * t);        // lrelu(ss + max sd) >= all row scores
        l[h] = 0.f;
        #pragma unroll
        for (int o = 0; o < NC; o++) acc[h][o] = 0.f;
    }

    const int* adjrow = adj + (size_t)row * NN;
    for (int j0 = 0; j0 < NN; j0 += K2_JC) {
        // stage Wh tile: 128 j x 32, as float4
        #pragma unroll
        for (int it = 0; it < 8; it++) {
            int idx = tid + it * K2_THREADS;
            int jj = idx >> 3, q = idx & 7;
            float4 v = *(const float4*)(g_Wh + (size_t)(j0 + jj) * NCOL + q * 4);
            float* d = sWh + jj * 36 + q * 4;
            d[0] = v.x; d[1] = v.y; d[2] = v.z; d[3] = v.w;
        }
        // stage s_dst tile
        #pragma unroll
        for (int it = 0; it < 4; it++) {
            int idx = tid + it * K2_THREADS;
            int h = idx >> 7, jj = idx & 127;
            ssd[h * K2_JC + jj] = g_sd[h * NN + j0 + jj];
        }
        __syncthreads();

        #pragma unroll 2
        for (int jj = s; jj < K2_JC; jj += 8) {
            int aij = adjrow[j0 + jj];
            if (aij > 0) {
                const float4* wp = (const float4*)(sWh + jj * 36);
                #pragma unroll
                for (int h = 0; h < NH; h++) {
                    float t  = ssr[h] + ssd[h * K2_JC + jj];
                    float lr = fmaxf(t, ALPHA * t);
                    float w  = __expf(lr - Mr[h]);
                    l[h] += w;
                    float4 wa = wp[h * 2], wb = wp[h * 2 + 1];
                    acc[h][0] += w * wa.x; acc[h][1] += w * wa.y;
                    acc[h][2] += w * wa.z; acc[h][3] += w * wa.w;
                    acc[h][4] += w * wb.x; acc[h][5] += w * wb.y;
                    acc[h][6] += w * wb.z; acc[h][7] += w * wb.w;
                }
            }
        }
        __syncthreads();
    }

    // reduce the 8 per-row threads (contiguous lanes in one warp)
    #pragma unroll
    for (int off = 4; off >= 1; off >>= 1) {
        #pragma unroll
        for (int h = 0; h < NH; h++) {
            l[h] += __shfl_down_sync(0xffffffffu, l[h], off);
            #pragma unroll
            for (int o = 0; o < NC; o++)
                acc[h][o] += __shfl_down_sync(0xffffffffu, acc[h][o], off);
        }
    }

    if (s == 0) {
        float inv[NH];
        #pragma unroll
        for (int h = 0; h < NH; h++) inv[h] = 1.f / l[h];
        float emb[NC];
        float m = -1e30f;
        #pragma unroll
        for (int o = 0; o < NC; o++) {
            float v = 0.f;
            #pragma unroll
            for (int h = 0; h < NH; h++) v += acc[h][o] * inv[h];
            v *= 0.25f;                               // mean over heads
            emb[o] = v;
            m = fmaxf(m, v);
            dout[8 + (size_t)row * NC + o] = v;       // node_embeddings
        }
        float sum = 0.f;
        #pragma unroll
        for (int o = 0; o < NC; o++) sum += expf(emb[o] - m);
        float lg = logf(sum) + m;
        #pragma unroll
        for (int o = 0; o < NC; o++) g_ls[(size_t)row * NC + o] = emb[o] - lg;
    }
}

// ---------------- K3: out[c] = sum_n ls[n][c] * w_lin[n] + b ----------------
__global__ void k3_out(const float* __restrict__ w_lin, const float* __restrict__ b_lin,
                       float* __restrict__ dout)
{
    __shared__ float red[8 * 256];
    const int tid = threadIdx.x;
    float acc[8] = {0.f, 0.f, 0.f, 0.f, 0.f, 0.f, 0.f, 0.f};
    for (int n = tid; n < NN; n += 256) {
        float wv = w_lin[n];
        #pragma unroll
        for (int c = 0; c < 8; c++) acc[c] += g_ls[n * 8 + c] * wv;
    }
    #pragma unroll
    for (int c = 0; c < 8; c++) red[c * 256 + tid] = acc[c];
    __syncthreads();
    for (int s2 = 128; s2 > 0; s2 >>= 1) {
        if (tid < s2) {
            #pragma unroll
            for (int c = 0; c < 8; c++) red[c * 256 + tid] += red[c * 256 + tid + s2];
        }
        __syncthreads();
    }
    if (tid < 8) dout[tid] = red[tid * 256] + b_lin[0];
}

extern "C" void kernel_launch(void* const* d_in, const int* in_sizes, int n_in,
                              void* d_out, int out_size)
{
    const float* x     = (const float*)d_in[0];
    const int*   adj   = (const int*)d_in[1];
    const float* W     = (const float*)d_in[2];
    const float* a     = (const float*)d_in[3];
    const float* w_lin = (const float*)d_in[4];
    const float* b_lin = (const float*)d_in[5];
    float* out = (float*)d_out;

    k1_gemm<<<NN / K1_ROWS, K1_THREADS>>>(x, W, a);
    k_smax<<<NH, 256>>>();
    k2_attn<<<NN / K2_ROWS, K2_THREADS>>>(adj, out);
    k3_out<<<1, 256>>>(w_lin, b_lin, out);
}

// round 2
// speedup vs baseline: 1.1743x; 1.1743x over previous
#include <cuda_runtime.h>
#include <math.h>

#define NN 4096
#define NFEAT 4096
#define NC 8
#define NH 4
#define NCOL 32
#define ALPHA 0.2f

// Scratch (no allocations allowed)
__device__ float g_Wh[NN * NCOL];     // [n][h*8+o]
__device__ float g_ss[NH * NN];       // s_src
__device__ float g_sd[NH * NN];       // s_dst
__device__ float g_smax[NH];          // global max of s_dst per head

// ---------------- K1: Wh = x @ W  (+ s_src / s_dst) ----------------
#define K1_ROWS 32
#define K1_KC 128
#define K1_THREADS 256

__global__ __launch_bounds__(K1_THREADS) void k1_gemm(
    const float* __restrict__ x, const float* __restrict__ W, const float* __restrict__ a)
{
    __shared__ float sx[K1_ROWS * 132];   // padded: conflict-free row broadcast
    __shared__ float sW[K1_KC * 32];
    const int tid = threadIdx.x;
    const int i0 = blockIdx.x * K1_ROWS;
    const int r = tid >> 3, g = tid & 7;  // 8 threads per row, 4 output cols each
    float acc0 = 0.f, acc1 = 0.f, acc2 = 0.f, acc3 = 0.f;

    for (int k0 = 0; k0 < NFEAT; k0 += K1_KC) {
        // x tile: 32 rows x 128 k  (1024 float4)
        #pragma unroll
        for (int it = 0; it < 4; it++) {
            int idx = tid + it * K1_THREADS;
            int rr = idx >> 5, kk4 = idx & 31;
            float4 v = *(const float4*)(x + (size_t)(i0 + rr) * NFEAT + k0 + kk4 * 4);
            float* d = sx + rr * 132 + kk4 * 4;
            d[0] = v.x; d[1] = v.y; d[2] = v.z; d[3] = v.w;
        }
        // W tile: 128 k x 32 cols (col = h*8+o), 1024 float4
        #pragma unroll
        for (int it = 0; it < 4; it++) {
            int idx = tid + it * K1_THREADS;
            int kk = idx >> 3, c4 = idx & 7;
            int h = c4 >> 1, o4 = (c4 & 1) * 4;
            float4 v = *(const float4*)(W + (size_t)h * NFEAT * NC + (size_t)(k0 + kk) * NC + o4);
            float* d = sW + kk * 32 + c4 * 4;
            d[0] = v.x; d[1] = v.y; d[2] = v.z; d[3] = v.w;
        }
        __syncthreads();
        const float* sxr = sx + r * 132;
        const float4* sW4 = (const float4*)sW;
        #pragma unroll 8
        for (int kk = 0; kk < K1_KC; kk++) {
            float xv = sxr[kk];
            float4 w4 = sW4[kk * 8 + g];
            acc0 += xv * w4.x; acc1 += xv * w4.y;
            acc2 += xv * w4.z; acc3 += xv * w4.w;
        }
        __syncthreads();
    }
    const int row = i0 + r;
    *(float4*)(g_Wh + (size_t)row * NCOL + g * 4) = make_float4(acc0, acc1, acc2, acc3);

    // s_src = Wh . a[h, :8],  s_dst = Wh . a[h, 8:]
    const int h = g >> 1;
    const int ob = (g & 1) * 4;
    const float* ah = a + h * 2 * NC;
    float ps = acc0 * ah[ob] + acc1 * ah[ob + 1] + acc2 * ah[ob + 2] + acc3 * ah[ob + 3];
    float pd = acc0 * ah[NC + ob] + acc1 * ah[NC + ob + 1] + acc2 * ah[NC + ob + 2] + acc3 * ah[NC + ob + 3];
    ps += __shfl_down_sync(0xffffffffu, ps, 1);
    pd += __shfl_down_sync(0xffffffffu, pd, 1);
    if ((g & 1) == 0) {
        g_ss[h * NN + row] = ps;
        g_sd[h * NN + row] = pd;
    }
}

// ---------------- K1b: global max of s_dst per head + out init ----------------
__global__ void k_smax(const float* __restrict__ b_lin, float* __restrict__ dout)
{
    __shared__ float sm[256];
    const int h = blockIdx.x, tid = threadIdx.x;
    if (h == 0 && tid < 8) dout[tid] = b_lin[0];   // init linear-out accumulators
    float m = -1e30f;
    for (int j = tid; j < NN; j += 256) m = fmaxf(m, g_sd[h * NN + j]);
    sm[tid] = m;
    __syncthreads();
    for (int s2 = 128; s2 > 0; s2 >>= 1) {
        if (tid < s2) sm[tid] = fmaxf(sm[tid], sm[tid + s2]);
        __syncthreads();
    }
    if (tid == 0) g_smax[h] = sm[0];
}

// ---------------- K2: masked softmax attention + aggregate + epilogue ----------------
#define K2_ROWS 16
#define K2_SPLIT 16
#define K2_JC 128
#define K2_THREADS 256

__global__ __launch_bounds__(K2_THREADS) void k2_attn(
    const int* __restrict__ adj, const float* __restrict__ w_lin, float* __restrict__ dout)
{
    __shared__ float sWh[K2_JC * 36];       // padded: phase-conflict-free float4 reads
    __shared__ float ssd[NH * K2_JC];
    const int tid = threadIdx.x;
    const int i0 = blockIdx.x * K2_ROWS;
    const int r = tid >> 4, s = tid & 15;   // 16 threads per row
    const int row = i0 + r;

    float ssr[NH], Mr[NH], l[NH];
    float acc[NH][NC];
    #pragma unroll
    for (int h = 0; h < NH; h++) {
        float ssv = g_ss[h * NN + row];
        ssr[h] = ssv;
        float t = ssv + g_smax[h];
        Mr[h] = fmaxf(t, ALPHA * t);        // lrelu(ss + max sd) >= all row scores
        l[h] = 0.f;
        #pragma unroll
        for (int o = 0; o < NC; o++) acc[h][o] = 0.f;
    }

    const int* adjrow = adj + (size_t)row * NN;
    for (int j0 = 0; j0 < NN; j0 += K2_JC) {
        // stage Wh tile: 128 j x 32 floats
        #pragma unroll
        for (int it = 0; it < 4; it++) {
            int idx = tid + it * K2_THREADS;
            int jj = idx >> 3, q = idx & 7;
            float4 v = *(const float4*)(g_Wh + (size_t)(j0 + jj) * NCOL + q * 4);
            float* d = sWh + jj * 36 + q * 4;
            d[0] = v.x; d[1] = v.y; d[2] = v.z; d[3] = v.w;
        }
        // stage s_dst tile
        #pragma unroll
        for (int it = 0; it < 2; it++) {
            int idx = tid + it * K2_THREADS;
            int h = idx >> 7, jj = idx & 127;
            ssd[h * K2_JC + jj] = g_sd[h * NN + j0 + jj];
        }
        __syncthreads();

        #pragma unroll 4
        for (int u = 0; u < K2_JC / K2_SPLIT; u++) {
            const int jj = s + u * K2_SPLIT;
            const int aij = adjrow[j0 + jj];
            const float4* wp = (const float4*)(sWh + jj * 36);
            #pragma unroll
            for (int h = 0; h < NH; h++) {
                float t  = ssr[h] + ssd[h * K2_JC + jj];
                float lr = fmaxf(t, ALPHA * t);
                float w  = __expf(lr - Mr[h]);
                w = (aij > 0) ? w : 0.f;    // branchless mask (SEL)
                l[h] += w;
                float4 wa = wp[h * 2], wb = wp[h * 2 + 1];
                acc[h][0] += w * wa.x; acc[h][1] += w * wa.y;
                acc[h][2] += w * wa.z; acc[h][3] += w * wa.w;
                acc[h][4] += w * wb.x; acc[h][5] += w * wb.y;
                acc[h][6] += w * wb.z; acc[h][7] += w * wb.w;
            }
        }
        __syncthreads();
    }

    // reduce the 16 per-row lanes (width-16 shuffle groups within each warp)
    #pragma unroll
    for (int off = 8; off >= 1; off >>= 1) {
        #pragma unroll
        for (int h = 0; h < NH; h++) {
            l[h] += __shfl_down_sync(0xffffffffu, l[h], off, 16);
            #pragma unroll
            for (int o = 0; o < NC; o++)
                acc[h][o] += __shfl_down_sync(0xffffffffu, acc[h][o], off, 16);
        }
    }

    if (s == 0) {
        float inv[NH];
        #pragma unroll
        for (int h = 0; h < NH; h++) inv[h] = 1.f / l[h];
        float emb[NC];
        float m = -1e30f;
        #pragma unroll
        for (int o = 0; o < NC; o++) {
            float v = 0.f;
            #pragma unroll
            for (int h = 0; h < NH; h++) v += acc[h][o] * inv[h];
            v *= 0.25f;                               // mean over heads
            emb[o] = v;
            m = fmaxf(m, v);
            dout[8 + (size_t)row * NC + o] = v;       // node_embeddings
        }
        float sum = 0.f;
        #pragma unroll
        for (int o = 0; o < NC; o++) sum += expf(emb[o] - m);
        float lg = logf(sum) + m;
        // fused final linear: out[c] += log_softmax(emb)[c] * w_lin[row]
        float wv = w_lin[row];
        #pragma unroll
        for (int o = 0; o < NC; o++) atomicAdd(&dout[o], (emb[o] - lg) * wv);
    }
}

extern "C" void kernel_launch(void* const* d_in, const int* in_sizes, int n_in,
                              void* d_out, int out_size)
{
    const float* x     = (const float*)d_in[0];
    const int*   adj   = (const int*)d_in[1];
    const float* W     = (const float*)d_in[2];
    const float* a     = (const float*)d_in[3];
    const float* w_lin = (const float*)d_in[4];
    const float* b_lin = (const float*)d_in[5];
    float* out = (float*)d_out;

    k1_gemm<<<NN / K1_ROWS, K1_THREADS>>>(x, W, a);
    k_smax<<<NH, 256>>>(b_lin, out);
    k2_attn<<<NN / K2_ROWS, K2_THREADS>>>(adj, w_lin, out);
}

// round 3
// speedup vs baseline: 1.5103x; 1.2862x over previous
#include <cuda_runtime.h>
#include <math.h>

#define NN 4096
#define NFEAT 4096
#define NC 8
#define NH 4
#define NCOL 32
#define ALPHA 0.2f
#define L2E 1.4426950408889634f

typedef unsigned long long ull;

// Scratch (no allocations allowed)
__device__ float g_Wh[NN * NCOL];     // [n][h*8+o]
__device__ float g_ss[NH * NN];       // s_src (raw)
__device__ float g_sd[NH * NN];       // s_dst (raw)
__device__ float g_smax[NH];          // global max of s_dst per head (raw)

// ---------------- K1: Wh = x @ W  (+ s_src / s_dst) ----------------
// 256 threads: warp = output col-quad (broadcast W loads), lane = row.
__global__ __launch_bounds__(256) void k1_gemm(
    const float* __restrict__ x, const float* __restrict__ W, const float* __restrict__ a)
{
    __shared__ float sx[32 * 132];    // 32 rows x 128 k, pad 132 (conflict-free float4)
    __shared__ float sW[128 * 32];    // 128 k x 32 cols
    const int tid = threadIdx.x;
    const int g = tid >> 5;           // warp id = col quad 0..7
    const int r = tid & 31;           // row 0..31
    const int i0 = blockIdx.x * 32;

    ull acc01 = 0ULL, acc23 = 0ULL;   // packed f32x2 accumulators (cols g*4+0..3)

    for (int k0 = 0; k0 < NFEAT; k0 += 128) {
        #pragma unroll
        for (int it = 0; it < 4; it++) {
            int idx = tid + it * 256;
            int rr = idx >> 5, kk4 = idx & 31;
            float4 v = *(const float4*)(x + (size_t)(i0 + rr) * NFEAT + k0 + kk4 * 4);
            *(float4*)(sx + rr * 132 + kk4 * 4) = v;
        }
        #pragma unroll
        for (int it = 0; it < 4; it++) {
            int idx = tid + it * 256;
            int kk = idx >> 3, c4 = idx & 7;
            int h = c4 >> 1, o4 = (c4 & 1) * 4;
            float4 v = *(const float4*)(W + (size_t)h * NFEAT * NC + (size_t)(k0 + kk) * NC + o4);
            *(float4*)(sW + kk * 32 + c4 * 4) = v;
        }
        __syncthreads();
        const float4* sxr = (const float4*)(sx + r * 132);
        #pragma unroll 8
        for (int kk4 = 0; kk4 < 32; kk4++) {
            float4 xv = sxr[kk4];                     // per-lane, conflict-free
            const float* wb = sW + kk4 * 4 * 32 + g * 4;
            ulonglong2 w0 = *(const ulonglong2*)(wb);         // broadcast within warp
            ulonglong2 w1 = *(const ulonglong2*)(wb + 32);
            ulonglong2 w2 = *(const ulonglong2*)(wb + 64);
            ulonglong2 w3 = *(const ulonglong2*)(wb + 96);
            ull s0, s1, s2, s3;
            asm("mov.b64 %0, {%1,%1};" : "=l"(s0) : "f"(xv.x));
            asm("mov.b64 %0, {%1,%1};" : "=l"(s1) : "f"(xv.y));
            asm("mov.b64 %0, {%1,%1};" : "=l"(s2) : "f"(xv.z));
            asm("mov.b64 %0, {%1,%1};" : "=l"(s3) : "f"(xv.w));
            asm("fma.rn.f32x2 %0, %1, %2, %0;" : "+l"(acc01) : "l"(w0.x), "l"(s0));
            asm("fma.rn.f32x2 %0, %1, %2, %0;" : "+l"(acc23) : "l"(w0.y), "l"(s0));
            asm("fma.rn.f32x2 %0, %1, %2, %0;" : "+l"(acc01) : "l"(w1.x), "l"(s1));
            asm("fma.rn.f32x2 %0, %1, %2, %0;" : "+l"(acc23) : "l"(w1.y), "l"(s1));
            asm("fma.rn.f32x2 %0, %1, %2, %0;" : "+l"(acc01) : "l"(w2.x), "l"(s2));
            asm("fma.rn.f32x2 %0, %1, %2, %0;" : "+l"(acc23) : "l"(w2.y), "l"(s2));
            asm("fma.rn.f32x2 %0, %1, %2, %0;" : "+l"(acc01) : "l"(w3.x), "l"(s3));
            asm("fma.rn.f32x2 %0, %1, %2, %0;" : "+l"(acc23) : "l"(w3.y), "l"(s3));
        }
        __syncthreads();
    }

    union { ull u; float2 f; } c01, c23;
    c01.u = acc01; c23.u = acc23;
    const int row = i0 + r;
    *(float4*)(g_Wh + (size_t)row * NCOL + g * 4) =
        make_float4(c01.f.x, c01.f.y, c23.f.x, c23.f.y);

    // exchange via smem (sx no longer read) to compute s_src/s_dst
    float* swp = sx;
    swp[r * 32 + g * 4 + 0] = c01.f.x;
    swp[r * 32 + g * 4 + 1] = c01.f.y;
    swp[r * 32 + g * 4 + 2] = c23.f.x;
    swp[r * 32 + g * 4 + 3] = c23.f.y;
    __syncthreads();
    if (tid < 128) {
        int r2 = tid >> 2, h = tid & 3;
        const float* wr = swp + r2 * 32 + h * 8;
        const float* ah = a + h * 2 * NC;
        float ss = 0.f, sd = 0.f;
        #pragma unroll
        for (int o = 0; o < 8; o++) { float v = wr[o]; ss += v * ah[o]; sd += v * ah[8 + o]; }
        g_ss[h * NN + i0 + r2] = ss;
        g_sd[h * NN + i0 + r2] = sd;
    }
}

// ---------------- K1b: global max of s_dst per head + out init ----------------
__global__ void k_smax(const float* __restrict__ b_lin, float* __restrict__ dout)
{
    __shared__ float sm[256];
    const int h = blockIdx.x, tid = threadIdx.x;
    if (h == 0 && tid < 8) dout[tid] = b_lin[0];
    float m = -1e30f;
    for (int j = tid; j < NN; j += 256) m = fmaxf(m, g_sd[h * NN + j]);
    sm[tid] = m;
    __syncthreads();
    for (int s2 = 128; s2 > 0; s2 >>= 1) {
        if (tid < s2) sm[tid] = fmaxf(sm[tid], sm[tid + s2]);
        __syncthreads();
    }
    if (tid == 0) g_smax[h] = sm[0];
}

// ---------------- K2: masked softmax attention + aggregate + epilogue ----------------
// 256 threads = 16 row-slots x 16 j-lanes; each thread owns 2 rows (r, r+16).
__global__ __launch_bounds__(256) void k2_attn(
    const int* __restrict__ adj, const float* __restrict__ w_lin, float* __restrict__ dout)
{
    __shared__ float sWh[128 * 36];   // pad 36: conflict-free LDS.128 phases
    __shared__ float ssd[NH * 128];   // pre-scaled by log2(e)
    const int tid = threadIdx.x;
    const int r = tid >> 4, s = tid & 15;
    const int i0 = blockIdx.x * 32;
    const int rowA = i0 + r, rowB = i0 + r + 16;

    float ssA[NH], ssB[NH], MA[NH], MB[NH], lA[NH], lB[NH];
    ull accA[NH][4], accB[NH][4];
    #pragma unroll
    for (int h = 0; h < NH; h++) {
        float sm = g_smax[h] * L2E;
        float sa = g_ss[h * NN + rowA] * L2E; ssA[h] = sa;
        float ta = sa + sm; MA[h] = fmaxf(ta, ALPHA * ta);
        float sb = g_ss[h * NN + rowB] * L2E; ssB[h] = sb;
        float tb = sb + sm; MB[h] = fmaxf(tb, ALPHA * tb);
        lA[h] = 0.f; lB[h] = 0.f;
        #pragma unroll
        for (int q = 0; q < 4; q++) { accA[h][q] = 0ULL; accB[h][q] = 0ULL; }
    }

    const int* adjA = adj + (size_t)rowA * NN;
    const int* adjB = adj + (size_t)rowB * NN;

    for (int j0 = 0; j0 < NN; j0 += 128) {
        #pragma unroll
        for (int it = 0; it < 4; it++) {
            int idx = tid + it * 256;
            int jj = idx >> 3, q = idx & 7;
            float4 v = *(const float4*)(g_Wh + (size_t)(j0 + jj) * NCOL + q * 4);
            *(float4*)(sWh + jj * 36 + q * 4) = v;
        }
        #pragma unroll
        for (int it = 0; it < 2; it++) {
            int idx = tid + it * 256;
            int h = idx >> 7, jj = idx & 127;
            ssd[h * 128 + jj] = g_sd[h * NN + j0 + jj] * L2E;
        }
        __syncthreads();

        #pragma unroll
        for (int u = 0; u < 8; u++) {
            const int jj = s + u * 16;
            const int aA = adjA[j0 + jj];
            const int aB = adjB[j0 + jj];
            const float* wrow = sWh + jj * 36;
            #pragma unroll
            for (int h = 0; h < NH; h++) {
                float sdv = ssd[h * 128 + jj];
                float tA = ssA[h] + sdv, tB = ssB[h] + sdv;
                float eA = fmaxf(tA, ALPHA * tA) - MA[h];
                float eB = fmaxf(tB, ALPHA * tB) - MB[h];
                float wA, wB;
                asm("ex2.approx.f32 %0, %1;" : "=f"(wA) : "f"(eA));
                asm("ex2.approx.f32 %0, %1;" : "=f"(wB) : "f"(eB));
                wA = (aA > 0) ? wA : 0.f;
                wB = (aB > 0) ? wB : 0.f;
                lA[h] += wA; lB[h] += wB;
                ull pA, pB;
                asm("mov.b64 %0, {%1,%1};" : "=l"(pA) : "f"(wA));
                asm("mov.b64 %0, {%1,%1};" : "=l"(pB) : "f"(wB));
                ulonglong2 w01 = *(const ulonglong2*)(wrow + h * 8);      // LDS.128
                ulonglong2 w23 = *(const ulonglong2*)(wrow + h * 8 + 4);  // LDS.128
                asm("fma.rn.f32x2 %0, %1, %2, %0;" : "+l"(accA[h][0]) : "l"(w01.x), "l"(pA));
                asm("fma.rn.f32x2 %0, %1, %2, %0;" : "+l"(accA[h][1]) : "l"(w01.y), "l"(pA));
                asm("fma.rn.f32x2 %0, %1, %2, %0;" : "+l"(accA[h][2]) : "l"(w23.x), "l"(pA));
                asm("fma.rn.f32x2 %0, %1, %2, %0;" : "+l"(accA[h][3]) : "l"(w23.y), "l"(pA));
                asm("fma.rn.f32x2 %0, %1, %2, %0;" : "+l"(accB[h][0]) : "l"(w01.x), "l"(pB));
                asm("fma.rn.f32x2 %0, %1, %2, %0;" : "+l"(accB[h][1]) : "l"(w01.y), "l"(pB));
                asm("fma.rn.f32x2 %0, %1, %2, %0;" : "+l"(accB[h][2]) : "l"(w23.x), "l"(pB));
                asm("fma.rn.f32x2 %0, %1, %2, %0;" : "+l"(accB[h][3]) : "l"(w23.y), "l"(pB));
            }
        }
        __syncthreads();
    }

    // width-16 reduction across j-lanes
    #pragma unroll
    for (int off = 8; off >= 1; off >>= 1) {
        #pragma unroll
        for (int h = 0; h < NH; h++) {
            lA[h] += __shfl_down_sync(0xffffffffu, lA[h], off, 16);
            lB[h] += __shfl_down_sync(0xffffffffu, lB[h], off, 16);
            #pragma unroll
            for (int q = 0; q < 4; q++) {
                ull tA = __shfl_down_sync(0xffffffffu, accA[h][q], off, 16);
                ull tB = __shfl_down_sync(0xffffffffu, accB[h][q], off, 16);
                asm("add.rn.f32x2 %0, %0, %1;" : "+l"(accA[h][q]) : "l"(tA));
                asm("add.rn.f32x2 %0, %0, %1;" : "+l"(accB[h][q]) : "l"(tB));
            }
        }
    }

    if (s == 0) {
        #pragma unroll
        for (int pr = 0; pr < 2; pr++) {
            const int row = pr ? rowB : rowA;
            float* lp = pr ? lB : lA;
            ull (*ac)[4] = pr ? accB : accA;
            float inv[NH];
            #pragma unroll
            for (int h = 0; h < NH; h++) inv[h] = 1.f / lp[h];
            float emb[NC], m = -1e30f;
            #pragma unroll
            for (int o = 0; o < NC; o++) {
                float v = 0.f;
                #pragma unroll
                for (int h = 0; h < NH; h++) {
                    union { ull u; float2 f; } cv; cv.u = ac[h][o >> 1];
                    v += ((o & 1) ? cv.f.y : cv.f.x) * inv[h];
                }
                v *= 0.25f;
                emb[o] = v; m = fmaxf(m, v);
                dout[8 + (size_t)row * NC + o] = v;
            }
            float sum = 0.f;
            #pragma unroll
            for (int o = 0; o < NC; o++) sum += expf(emb[o] - m);
            float lg = logf(sum) + m;
            float wv = w_lin[row];
            #pragma unroll
            for (int o = 0; o < NC; o++) atomicAdd(&dout[o], (emb[o] - lg) * wv);
        }
    }
}

extern "C" void kernel_launch(void* const* d_in, const int* in_sizes, int n_in,
                              void* d_out, int out_size)
{
    const float* x     = (const float*)d_in[0];
    const int*   adj   = (const int*)d_in[1];
    const float* W     = (const float*)d_in[2];
    const float* a     = (const float*)d_in[3];
    const float* w_lin = (const float*)d_in[4];
    const float* b_lin = (const float*)d_in[5];
    float* out = (float*)d_out;

    k1_gemm<<<NN / 32, 256>>>(x, W, a);
    k_smax<<<NH, 256>>>(b_lin, out);
    k2_attn<<<NN / 32, 256>>>(adj, w_lin, out);
}

// round 4
// speedup vs baseline: 1.5119x; 1.0011x over previous
#include <cuda_runtime.h>
#include <math.h>

#define NN 4096
#define NFEAT 4096
#define NC 8
#define NH 4
#define NCOL 32
#define ALPHA 0.2f
#define L2E 1.4426950408889634f

typedef unsigned long long ull;

// Scratch (no allocations allowed)
__device__ float g_Wh[NN * NCOL];     // [n][h*8+o]
__device__ float g_ss[NH * NN];       // s_src (raw)
__device__ float g_sd[NH * NN];       // s_dst (raw)
__device__ float g_smax[NH];          // global max of s_dst per head (raw)

// ---------------- K1: Wh = x @ W  (+ s_src / s_dst) ----------------
// 256 threads: warp = output col-quad (broadcast W loads), lane = row.
__global__ __launch_bounds__(256) void k1_gemm(
    const float* __restrict__ x, const float* __restrict__ W, const float* __restrict__ a)
{
    __shared__ float sx[32 * 132];    // 32 rows x 128 k, pad 132 (conflict-free float4)
    __shared__ float sW[128 * 32];    // 128 k x 32 cols
    const int tid = threadIdx.x;
    const int g = tid >> 5;           // warp id = col quad 0..7
    const int r = tid & 31;           // row 0..31
    const int i0 = blockIdx.x * 32;

    ull acc01 = 0ULL, acc23 = 0ULL;   // packed f32x2 accumulators (cols g*4+0..3)

    for (int k0 = 0; k0 < NFEAT; k0 += 128) {
        #pragma unroll
        for (int it = 0; it < 4; it++) {
            int idx = tid + it * 256;
            int rr = idx >> 5, kk4 = idx & 31;
            float4 v = *(const float4*)(x + (size_t)(i0 + rr) * NFEAT + k0 + kk4 * 4);
            *(float4*)(sx + rr * 132 + kk4 * 4) = v;
        }
        #pragma unroll
        for (int it = 0; it < 4; it++) {
            int idx = tid + it * 256;
            int kk = idx >> 3, c4 = idx & 7;
            int h = c4 >> 1, o4 = (c4 & 1) * 4;
            float4 v = *(const float4*)(W + (size_t)h * NFEAT * NC + (size_t)(k0 + kk) * NC + o4);
            *(float4*)(sW + kk * 32 + c4 * 4) = v;
        }
        __syncthreads();
        const float4* sxr = (const float4*)(sx + r * 132);
        #pragma unroll 8
        for (int kk4 = 0; kk4 < 32; kk4++) {
            float4 xv = sxr[kk4];                     // per-lane, conflict-free
            const float* wb = sW + kk4 * 4 * 32 + g * 4;
            ulonglong2 w0 = *(const ulonglong2*)(wb);         // broadcast within warp
            ulonglong2 w1 = *(const ulonglong2*)(wb + 32);
            ulonglong2 w2 = *(const ulonglong2*)(wb + 64);
            ulonglong2 w3 = *(const ulonglong2*)(wb + 96);
            ull s0, s1, s2, s3;
            asm("mov.b64 %0, {%1,%1};" : "=l"(s0) : "f"(xv.x));
            asm("mov.b64 %0, {%1,%1};" : "=l"(s1) : "f"(xv.y));
            asm("mov.b64 %0, {%1,%1};" : "=l"(s2) : "f"(xv.z));
            asm("mov.b64 %0, {%1,%1};" : "=l"(s3) : "f"(xv.w));
            asm("fma.rn.f32x2 %0, %1, %2, %0;" : "+l"(acc01) : "l"(w0.x), "l"(s0));
            asm("fma.rn.f32x2 %0, %1, %2, %0;" : "+l"(acc23) : "l"(w0.y), "l"(s0));
            asm("fma.rn.f32x2 %0, %1, %2, %0;" : "+l"(acc01) : "l"(w1.x), "l"(s1));
            asm("fma.rn.f32x2 %0, %1, %2, %0;" : "+l"(acc23) : "l"(w1.y), "l"(s1));
            asm("fma.rn.f32x2 %0, %1, %2, %0;" : "+l"(acc01) : "l"(w2.x), "l"(s2));
            asm("fma.rn.f32x2 %0, %1, %2, %0;" : "+l"(acc23) : "l"(w2.y), "l"(s2));
            asm("fma.rn.f32x2 %0, %1, %2, %0;" : "+l"(acc01) : "l"(w3.x), "l"(s3));
            asm("fma.rn.f32x2 %0, %1, %2, %0;" : "+l"(acc23) : "l"(w3.y), "l"(s3));
        }
        __syncthreads();
    }

    union { ull u; float2 f; } c01, c23;
    c01.u = acc01; c23.u = acc23;
    const int row = i0 + r;
    *(float4*)(g_Wh + (size_t)row * NCOL + g * 4) =
        make_float4(c01.f.x, c01.f.y, c23.f.x, c23.f.y);

    // exchange via smem (sx no longer read) to compute s_src/s_dst
    float* swp = sx;
    swp[r * 32 + g * 4 + 0] = c01.f.x;
    swp[r * 32 + g * 4 + 1] = c01.f.y;
    swp[r * 32 + g * 4 + 2] = c23.f.x;
    swp[r * 32 + g * 4 + 3] = c23.f.y;
    __syncthreads();
    if (tid < 128) {
        int r2 = tid >> 2, h = tid & 3;
        const float* wr = swp + r2 * 32 + h * 8;
        const float* ah = a + h * 2 * NC;
        float ss = 0.f, sd = 0.f;
        #pragma unroll
        for (int o = 0; o < 8; o++) { float v = wr[o]; ss += v * ah[o]; sd += v * ah[8 + o]; }
        g_ss[h * NN + i0 + r2] = ss;
        g_sd[h * NN + i0 + r2] = sd;
    }
}

// ---------------- K1b: global max of s_dst per head + out init ----------------
__global__ void k_smax(const float* __restrict__ b_lin, float* __restrict__ dout)
{
    __shared__ float sm[256];
    const int h = blockIdx.x, tid = threadIdx.x;
    if (h == 0 && tid < 8) dout[tid] = b_lin[0];
    float m = -1e30f;
    for (int j = tid; j < NN; j += 256) m = fmaxf(m, g_sd[h * NN + j]);
    sm[tid] = m;
    __syncthreads();
    for (int s2 = 128; s2 > 0; s2 >>= 1) {
        if (tid < s2) sm[tid] = fmaxf(sm[tid], sm[tid + s2]);
        __syncthreads();
    }
    if (tid == 0) g_smax[h] = sm[0];
}

// ---------------- K2: masked softmax attention + aggregate + epilogue ----------------
// 256 threads = 16 row-slots x 16 j-lanes; each thread owns 2 rows (r, r+16).
__global__ __launch_bounds__(256) void k2_attn(
    const int* __restrict__ adj, const float* __restrict__ w_lin, float* __restrict__ dout)
{
    __shared__ float sWh[128 * 36];   // pad 36: conflict-free LDS.128 phases
    __shared__ float ssd[NH * 128];   // pre-scaled by log2(e)
    const int tid = threadIdx.x;
    const int r = tid >> 4, s = tid & 15;
    const int i0 = blockIdx.x * 32;
    const int rowA = i0 + r, rowB = i0 + r + 16;

    float ssA[NH], ssB[NH], MA[NH], MB[NH], lA[NH], lB[NH];
    ull accA[NH][4], accB[NH][4];
    #pragma unroll
    for (int h = 0; h < NH; h++) {
        float sm = g_smax[h] * L2E;
        float sa = g_ss[h * NN + rowA] * L2E; ssA[h] = sa;
        float ta = sa + sm; MA[h] = fmaxf(ta, ALPHA * ta);
        float sb = g_ss[h * NN + rowB] * L2E; ssB[h] = sb;
        float tb = sb + sm; MB[h] = fmaxf(tb, ALPHA * tb);
        lA[h] = 0.f; lB[h] = 0.f;
        #pragma unroll
        for (int q = 0; q < 4; q++) { accA[h][q] = 0ULL; accB[h][q] = 0ULL; }
    }

    const int* adjA = adj + (size_t)rowA * NN;
    const int* adjB = adj + (size_t)rowB * NN;

    for (int j0 = 0; j0 < NN; j0 += 128) {
        #pragma unroll
        for (int it = 0; it < 4; it++) {
            int idx = tid + it * 256;
            int jj = idx >> 3, q = idx & 7;
            float4 v = *(const float4*)(g_Wh + (size_t)(j0 + jj) * NCOL + q * 4);
            *(float4*)(sWh + jj * 36 + q * 4) = v;
        }
        #pragma unroll
        for (int it = 0; it < 2; it++) {
            int idx = tid + it * 256;
            int h = idx >> 7, jj = idx & 127;
            ssd[h * 128 + jj] = g_sd[h * NN + j0 + jj] * L2E;
        }
        __syncthreads();

        #pragma unroll
        for (int u = 0; u < 8; u++) {
            const int jj = s + u * 16;
            const int aA = adjA[j0 + jj];
            const int aB = adjB[j0 + jj];
            const float* wrow = sWh + jj * 36;
            #pragma unroll
            for (int h = 0; h < NH; h++) {
                float sdv = ssd[h * 128 + jj];
                float tA = ssA[h] + sdv, tB = ssB[h] + sdv;
                float eA = fmaxf(tA, ALPHA * tA) - MA[h];
                float eB = fmaxf(tB, ALPHA * tB) - MB[h];
                float wA, wB;
                asm("ex2.approx.f32 %0, %1;" : "=f"(wA) : "f"(eA));
                asm("ex2.approx.f32 %0, %1;" : "=f"(wB) : "f"(eB));
                wA = (aA > 0) ? wA : 0.f;
                wB = (aB > 0) ? wB : 0.f;
                lA[h] += wA; lB[h] += wB;
                ull pA, pB;
                asm("mov.b64 %0, {%1,%1};" : "=l"(pA) : "f"(wA));
                asm("mov.b64 %0, {%1,%1};" : "=l"(pB) : "f"(wB));
                ulonglong2 w01 = *(const ulonglong2*)(wrow + h * 8);      // LDS.128
                ulonglong2 w23 = *(const ulonglong2*)(wrow + h * 8 + 4);  // LDS.128
                asm("fma.rn.f32x2 %0, %1, %2, %0;" : "+l"(accA[h][0]) : "l"(w01.x), "l"(pA));
                asm("fma.rn.f32x2 %0, %1, %2, %0;" : "+l"(accA[h][1]) : "l"(w01.y), "l"(pA));
                asm("fma.rn.f32x2 %0, %1, %2, %0;" : "+l"(accA[h][2]) : "l"(w23.x), "l"(pA));
                asm("fma.rn.f32x2 %0, %1, %2, %0;" : "+l"(accA[h][3]) : "l"(w23.y), "l"(pA));
                asm("fma.rn.f32x2 %0, %1, %2, %0;" : "+l"(accB[h][0]) : "l"(w01.x), "l"(pB));
                asm("fma.rn.f32x2 %0, %1, %2, %0;" : "+l"(accB[h][1]) : "l"(w01.y), "l"(pB));
                asm("fma.rn.f32x2 %0, %1, %2, %0;" : "+l"(accB[h][2]) : "l"(w23.x), "l"(pB));
                asm("fma.rn.f32x2 %0, %1, %2, %0;" : "+l"(accB[h][3]) : "l"(w23.y), "l"(pB));
            }
        }
        __syncthreads();
    }

    // width-16 reduction across j-lanes
    #pragma unroll
    for (int off = 8; off >= 1; off >>= 1) {
        #pragma unroll
        for (int h = 0; h < NH; h++) {
            lA[h] += __shfl_down_sync(0xffffffffu, lA[h], off, 16);
            lB[h] += __shfl_down_sync(0xffffffffu, lB[h], off, 16);
            #pragma unroll
            for (int q = 0; q < 4; q++) {
                ull tA = __shfl_down_sync(0xffffffffu, accA[h][q], off, 16);
                ull tB = __shfl_down_sync(0xffffffffu, accB[h][q], off, 16);
                asm("add.rn.f32x2 %0, %0, %1;" : "+l"(accA[h][q]) : "l"(tA));
                asm("add.rn.f32x2 %0, %0, %1;" : "+l"(accB[h][q]) : "l"(tB));
            }
        }
    }

    if (s == 0) {
        #pragma unroll
        for (int pr = 0; pr < 2; pr++) {
            const int row = pr ? rowB : rowA;
            float* lp = pr ? lB : lA;
            ull (*ac)[4] = pr ? accB : accA;
            float inv[NH];
            #pragma unroll
            for (int h = 0; h < NH; h++) inv[h] = 1.f / lp[h];
            float emb[NC], m = -1e30f;
            #pragma unroll
            for (int o = 0; o < NC; o++) {
                float v = 0.f;
                #pragma unroll
                for (int h = 0; h < NH; h++) {
                    union { ull u; float2 f; } cv; cv.u = ac[h][o >> 1];
                    v += ((o & 1) ? cv.f.y : cv.f.x) * inv[h];
                }
                v *= 0.25f;
                emb[o] = v; m = fmaxf(m, v);
                dout[8 + (size_t)row * NC + o] = v;
            }
            float sum = 0.f;
            #pragma unroll
            for (int o = 0; o < NC; o++) sum += expf(emb[o] - m);
            float lg = logf(sum) + m;
            float wv = w_lin[row];
            #pragma unroll
            for (int o = 0; o < NC; o++) atomicAdd(&dout[o], (emb[o] - lg) * wv);
        }
    }
}

extern "C" void kernel_launch(void* const* d_in, const int* in_sizes, int n_in,
                              void* d_out, int out_size)
{
    const float* x     = (const float*)d_in[0];
    const int*   adj   = (const int*)d_in[1];
    const float* W     = (const float*)d_in[2];
    const float* a     = (const float*)d_in[3];
    const float* w_lin = (const float*)d_in[4];
    const float* b_lin = (const float*)d_in[5];
    float* out = (float*)d_out;

    k1_gemm<<<NN / 32, 256>>>(x, W, a);
    k_smax<<<NH, 256>>>(b_lin, out);
    k2_attn<<<NN / 32, 256>>>(adj, w_lin, out);
}